// round 15
// baseline (speedup 1.0000x reference)
#include <cuda_runtime.h>
#include <cuda_bf16.h>
#include <cstdint>
#include <cstddef>

// Problem constants (shapes fixed by the dataset).
#define B_    256
#define DIN_  512
#define H_    1024
#define DOUT_ 512
#define T_    256

// ---------------------------------------------------------------------------
// Device scratch. hs: T+1 slabs of [B, H] split bf16 (hi+lo).
// GRU weights gate-merged (4 blocks of H rows): 0: W_ir+W_hr, 1: W_iz+W_hz,
// 2: W_in, 3: W_hn.
// ---------------------------------------------------------------------------
__device__ __nv_bfloat16 g_hs_hi[(size_t)(T_ + 1) * B_ * H_];
__device__ __nv_bfloat16 g_hs_lo[(size_t)(T_ + 1) * B_ * H_];
__device__ __nv_bfloat16 g_W4hi[(size_t)4 * H_ * H_];
__device__ __nv_bfloat16 g_W4lo[(size_t)4 * H_ * H_];
__device__ __nv_bfloat16 g_xhi[B_ * DIN_],  g_xlo[B_ * DIN_];
__device__ __nv_bfloat16 g_w1hi[H_ * DIN_], g_w1lo[H_ * DIN_];
__device__ __nv_bfloat16 g_w2hi[H_ * H_],   g_w2lo[H_ * H_];
__device__ __nv_bfloat16 g_t1hi[B_ * H_],   g_t1lo[B_ * H_];
__device__ __nv_bfloat16 g_owhi[DOUT_ * H_], g_owlo[DOUT_ * H_];

// ---------------------------------------------------------------------------
// Split of x, w1, w2, out_w into bf16 hi/lo.
// ---------------------------------------------------------------------------
#define SPLIT_TOTAL 2228224
__global__ void split_all_kernel(const float* __restrict__ x,
                                 const float* __restrict__ w1,
                                 const float* __restrict__ w2,
                                 const float* __restrict__ ow) {
    int i = blockIdx.x * blockDim.x + threadIdx.x;
    if (i >= SPLIT_TOTAL) return;
    const float* src;
    __nv_bfloat16 *hi, *lo;
    int off;
    if (i < 131072)        { src = x;   hi = g_xhi;  lo = g_xlo;  off = i; }
    else if (i < 655360)   { src = w1;  hi = g_w1hi; lo = g_w1lo; off = i - 131072; }
    else if (i < 1703936)  { src = w2;  hi = g_w2hi; lo = g_w2lo; off = i - 655360; }
    else                   { src = ow;  hi = g_owhi; lo = g_owlo; off = i - 1703936; }
    float v = src[off];
    __nv_bfloat16 h = __float2bfloat16(v);
    hi[off] = h;
    lo[off] = __float2bfloat16(v - __bfloat162float(h));
}

// ---------------------------------------------------------------------------
// Gate-merged GRU weight prep: 4H rows, fp32 sums then exact hi/lo split.
// ---------------------------------------------------------------------------
__global__ void wprep4_kernel(const float* __restrict__ wih,
                              const float* __restrict__ whh) {
    int row = blockIdx.x;                  // 0 .. 4H-1
    int gate = row >> 10;
    int j    = row & (H_ - 1);
    for (int i = threadIdx.x; i < H_; i += 256) {
        float v;
        if (gate == 0)      v = wih[(size_t)j * H_ + i]            + whh[(size_t)j * H_ + i];
        else if (gate == 1) v = wih[(size_t)(H_ + j) * H_ + i]     + whh[(size_t)(H_ + j) * H_ + i];
        else if (gate == 2) v = wih[(size_t)(2 * H_ + j) * H_ + i];
        else                v = whh[(size_t)(2 * H_ + j) * H_ + i];
        __nv_bfloat16 h = __float2bfloat16(v);
        size_t idx = (size_t)row * H_ + i;
        g_W4hi[idx] = h;
        g_W4lo[idx] = __float2bfloat16(v - __bfloat162float(h));
    }
}

// ---------------------------------------------------------------------------
// PTX helpers
// ---------------------------------------------------------------------------
__device__ __forceinline__ void mma_bf16(float* c,
                                         uint32_t a0, uint32_t a1, uint32_t a2, uint32_t a3,
                                         uint32_t b0, uint32_t b1) {
    asm volatile(
        "mma.sync.aligned.m16n8k16.row.col.f32.bf16.bf16.f32 "
        "{%0,%1,%2,%3}, {%4,%5,%6,%7}, {%8,%9}, {%0,%1,%2,%3};\n"
        : "+f"(c[0]), "+f"(c[1]), "+f"(c[2]), "+f"(c[3])
        : "r"(a0), "r"(a1), "r"(a2), "r"(a3), "r"(b0), "r"(b1));
}
__device__ __forceinline__ void ldsm4(uint32_t& r0, uint32_t& r1,
                                      uint32_t& r2, uint32_t& r3, uint32_t addr) {
    asm volatile("ldmatrix.sync.aligned.m8n8.x4.shared.b16 {%0,%1,%2,%3}, [%4];\n"
                 : "=r"(r0), "=r"(r1), "=r"(r2), "=r"(r3) : "r"(addr));
}
__device__ __forceinline__ void cp16(uint32_t dst, const void* src) {
    asm volatile("cp.async.cg.shared.global [%0], [%1], 16;\n" :: "r"(dst), "l"(src));
}
__device__ __forceinline__ void cp_commit() {
    asm volatile("cp.async.commit_group;\n");
}
template <int N>
__device__ __forceinline__ void cp_wait() {
    asm volatile("cp.async.wait_group %0;\n" :: "n"(N));
}
__device__ __forceinline__ float sigm(float x) { return 1.0f / (1.0f + __expf(-x)); }
__device__ __forceinline__ float tanh_fast(float x) {
    float a = fabsf(x);
    float e = __expf(-2.0f * a);
    return copysignf((1.0f - e) / (1.0f + e), x);
}

// ---------------------------------------------------------------------------
// Split-bf16 GEMM (proven). BM=128, BN=64, BK=32; 256 threads.
// ---------------------------------------------------------------------------
__global__ __launch_bounds__(256, 2) void gemm3_kernel(
    int which, const float* __restrict__ bias, float* __restrict__ outf,
    int M, int N, int K, int mode)
{
    const __nv_bfloat16 *Ahi, *Alo, *Bhi, *Blo;
    if (which == 0)      { Ahi = g_xhi;  Alo = g_xlo;  Bhi = g_w1hi; Blo = g_w1lo; }
    else if (which == 1) { Ahi = g_t1hi; Alo = g_t1lo; Bhi = g_w2hi; Blo = g_w2lo; }
    else                 { Ahi = g_hs_hi + (size_t)B_ * H_; Alo = g_hs_lo + (size_t)B_ * H_;
                           Bhi = g_owhi; Blo = g_owlo; }
    const uint32_t* A32h = (const uint32_t*)Ahi;
    const uint32_t* A32l = (const uint32_t*)Alo;
    const uint32_t* B32h = (const uint32_t*)Bhi;
    const uint32_t* B32l = (const uint32_t*)Blo;

    __shared__ uint32_t sAh[128 * 20], sAl[128 * 20];
    __shared__ uint32_t sBh[64 * 20],  sBl[64 * 20];

    int tid  = threadIdx.x;
    int lane = tid & 31, warp = tid >> 5;
    int g = lane >> 2, t4 = lane & 3;
    int wm = warp >> 1, wn = warp & 1;
    int m0 = blockIdx.y * 128;
    int n0 = blockIdx.x * 64;
    int K2 = K >> 1;

    float acc[2][4][4];
#pragma unroll
    for (int a = 0; a < 2; a++)
#pragma unroll
        for (int b = 0; b < 4; b++)
#pragma unroll
            for (int c = 0; c < 4; c++) acc[a][b][c] = 0.0f;

    for (int k0 = 0; k0 < K; k0 += 32) {
        __syncthreads();
        int kc = k0 >> 1;
#pragma unroll
        for (int i = 0; i < 8; i++) {
            int e = tid + i * 256;
            int r = e >> 4, c = e & 15;
            size_t gi = (size_t)(m0 + r) * K2 + kc + c;
            sAh[r * 20 + c] = A32h[gi];
            sAl[r * 20 + c] = A32l[gi];
        }
#pragma unroll
        for (int i = 0; i < 4; i++) {
            int e = tid + i * 256;
            int r = e >> 4, c = e & 15;
            size_t gi = (size_t)(n0 + r) * K2 + kc + c;
            sBh[r * 20 + c] = B32h[gi];
            sBl[r * 20 + c] = B32l[gi];
        }
        __syncthreads();

#pragma unroll
        for (int kk = 0; kk < 2; kk++) {
            int base = kk * 8 + t4;
            uint32_t ah[2][4], al[2][4], bh[4][2], bl[4][2];
#pragma unroll
            for (int mf = 0; mf < 2; mf++) {
                int rb = wm * 32 + mf * 16;
                ah[mf][0] = sAh[(rb + g) * 20 + base];
                ah[mf][1] = sAh[(rb + g + 8) * 20 + base];
                ah[mf][2] = sAh[(rb + g) * 20 + base + 4];
                ah[mf][3] = sAh[(rb + g + 8) * 20 + base + 4];
                al[mf][0] = sAl[(rb + g) * 20 + base];
                al[mf][1] = sAl[(rb + g + 8) * 20 + base];
                al[mf][2] = sAl[(rb + g) * 20 + base + 4];
                al[mf][3] = sAl[(rb + g + 8) * 20 + base + 4];
            }
#pragma unroll
            for (int nf = 0; nf < 4; nf++) {
                int nb = wn * 32 + nf * 8 + g;
                bh[nf][0] = sBh[nb * 20 + base];
                bh[nf][1] = sBh[nb * 20 + base + 4];
                bl[nf][0] = sBl[nb * 20 + base];
                bl[nf][1] = sBl[nb * 20 + base + 4];
            }
#pragma unroll
            for (int mf = 0; mf < 2; mf++)
#pragma unroll
                for (int nf = 0; nf < 4; nf++)
                    mma_bf16(acc[mf][nf], ah[mf][0], ah[mf][1], ah[mf][2], ah[mf][3],
                             bh[nf][0], bh[nf][1]);
#pragma unroll
            for (int mf = 0; mf < 2; mf++)
#pragma unroll
                for (int nf = 0; nf < 4; nf++)
                    mma_bf16(acc[mf][nf], ah[mf][0], ah[mf][1], ah[mf][2], ah[mf][3],
                             bl[nf][0], bl[nf][1]);
#pragma unroll
            for (int mf = 0; mf < 2; mf++)
#pragma unroll
                for (int nf = 0; nf < 4; nf++)
                    mma_bf16(acc[mf][nf], al[mf][0], al[mf][1], al[mf][2], al[mf][3],
                             bh[nf][0], bh[nf][1]);
        }
    }

#pragma unroll
    for (int mf = 0; mf < 2; mf++)
#pragma unroll
        for (int nf = 0; nf < 4; nf++)
#pragma unroll
            for (int rr = 0; rr < 2; rr++)
#pragma unroll
                for (int cc = 0; cc < 2; cc++) {
                    int row = m0 + wm * 32 + mf * 16 + g + rr * 8;
                    int col = n0 + wn * 32 + nf * 8 + 2 * t4 + cc;
                    float v = acc[mf][nf][rr * 2 + cc] + bias[col];
                    if (mode == 0) {
                        __nv_bfloat16 h = __float2bfloat16(v);
                        g_t1hi[(size_t)row * N + col] = h;
                        g_t1lo[(size_t)row * N + col] =
                            __float2bfloat16(v - __bfloat162float(h));
                    } else if (mode == 1) {
                        outf[(size_t)row * N + col] = v;
                        __nv_bfloat16 h = __float2bfloat16(v);
                        g_hs_hi[(size_t)row * N + col] = h;
                        g_hs_lo[(size_t)row * N + col] =
                            __float2bfloat16(v - __bfloat162float(h));
                    } else {
                        int t = row >> 8;               // row = t*B + b
                        int b = row & 255;
                        int Trt = M >> 8;
                        outf[(size_t)b * Trt * N + (size_t)t * N + col] = v;
                    }
                }
}

// ---------------------------------------------------------------------------
// Fused GRU step — gate-merged, asymmetric precision, balanced warp split.
// BM=64, BN=16, grid (64, 4) = 256 CTAs, 2 CTAs/SM, 4-stage cp.async.
// Product units (10): r{hh,hl} z{hh,hl} i_n{hh,hl,lh} h_n{hh,hl,lh}
//   group 0 (warps 0-3): r(8 HMMA) + z(8) + i_n-hh(4)      = 20 HMMA, 12 LDSM
//   group 1 (warps 4-7): i_n-{hl,lh}(8) + h_n(12)          = 20 HMMA, 12 LDSM
// r/z drop the al*bh product (sigma gates tolerate ~3e-4 pre-act error).
// i_n accumulator is split across groups and summed in the smem exchange.
// ---------------------------------------------------------------------------
#define STAGES  4
#define R_BUF   (256 * 20)                 // u32 per stage (5120)
#define R_SMEM  (STAGES * R_BUF * 4)       // 81920 bytes dynamic

__global__ __launch_bounds__(256, 2) void gru_kernel(
    int t, const float* __restrict__ b_ih, const float* __restrict__ b_hh)
{
    extern __shared__ uint32_t smem[];

    int tid  = threadIdx.x;
    int lane = tid & 31, warp = tid >> 5;
    int g = lane >> 2, t4 = lane & 3;
    int warp_m = warp & 3, warp_g = warp >> 2;
    int m0 = blockIdx.y * 64;
    int j0 = blockIdx.x * 16;
    uint32_t sb = (uint32_t)__cvta_generic_to_shared(smem);

    // ---- per-thread load plan: 4 x 16B chunks per k32 tile ----
    const uint4* srcp[4];
    uint32_t     soff[4];
#pragma unroll
    for (int i = 0; i < 4; i++) {
        int c = tid + i * 256;             // 0..1023
        if (c < 512) {                     // A (h): hi then lo, 64 rows x 4 chunks
            int half = c >> 8, rem = c & 255;
            int row = rem >> 2, ch = rem & 3;
            const __nv_bfloat16* base =
                (half ? g_hs_lo : g_hs_hi) + (size_t)t * B_ * H_;
            srcp[i] = (const uint4*)base + (size_t)(m0 + row) * 128 + ch;
            soff[i] = (uint32_t)(half * 1280 + row * 20 + ch * 4) * 4;
        } else {                           // W4: hi then lo, 64 rows x 4 chunks
            int c2 = c - 512;
            int half = c2 >> 8, rem = c2 & 255;
            int row = rem >> 2, ch = rem & 3;
            int gate = row >> 4, rj = row & 15;
            const __nv_bfloat16* base = half ? g_W4lo : g_W4hi;
            srcp[i] = (const uint4*)base + (size_t)(gate * H_ + j0 + rj) * 128 + ch;
            soff[i] = (uint32_t)(2560 + half * 1280 + row * 20 + ch * 4) * 4;
        }
    }

    // LDSM address bases (byte offsets within a stage)
    int rb = warp_m * 16;
    uint32_t a_base = (uint32_t)((rb + (lane & 15)) * 80 + (lane >> 4) * 16);
    int q = lane >> 3;
    uint32_t b_base = (uint32_t)(10240 + (lane & 7) * 80 + (q >> 1) * 32 + (q & 1) * 16);

    // group 0: acc[0]=r, acc[1]=z, acc[2]=i_n(hh part)
    // group 1: acc[0]=i_n(hl+lh part), acc[1]=h_n, acc[2] unused
    float acc[3][2][4];
#pragma unroll
    for (int a = 0; a < 3; a++)
#pragma unroll
        for (int b = 0; b < 2; b++)
#pragma unroll
            for (int c = 0; c < 4; c++) acc[a][b][c] = 0.0f;

    auto load_tile = [&](int kt) {
        if (kt < 32) {
            uint32_t sbase = sb + (uint32_t)(kt & (STAGES - 1)) * (R_BUF * 4);
#pragma unroll
            for (int i = 0; i < 4; i++)
                cp16(sbase + soff[i], srcp[i] + kt * 4);
        }
        cp_commit();
    };

    load_tile(0);
    load_tile(1);
    load_tile(2);

    for (int kt = 0; kt < 32; kt++) {
        cp_wait<2>();
        __syncthreads();
        load_tile(kt + 3);

        uint32_t bufB = sb + (uint32_t)(kt & (STAGES - 1)) * (R_BUF * 4);

        uint32_t ah[2][4];
#pragma unroll
        for (int kk = 0; kk < 2; kk++)
            ldsm4(ah[kk][0], ah[kk][1], ah[kk][2], ah[kk][3],
                  bufB + a_base + kk * 32);

        if (warp_g == 0) {
            // r and z: hh + hl products (2 each)
#pragma unroll
            for (int gi = 0; gi < 2; gi++) {
                uint32_t baddr = bufB + b_base + (uint32_t)((gi * 16) * 80);
                uint32_t bh0[4], bl0[4], bh1[4], bl1[4];
                ldsm4(bh0[0], bh0[1], bh0[2], bh0[3], baddr);
                ldsm4(bl0[0], bl0[1], bl0[2], bl0[3], baddr + 5120);
                ldsm4(bh1[0], bh1[1], bh1[2], bh1[3], baddr + 640);
                ldsm4(bl1[0], bl1[1], bl1[2], bl1[3], baddr + 640 + 5120);
                mma_bf16(acc[gi][0], ah[0][0], ah[0][1], ah[0][2], ah[0][3], bh0[0], bh0[1]);
                mma_bf16(acc[gi][1], ah[0][0], ah[0][1], ah[0][2], ah[0][3], bh1[0], bh1[1]);
                mma_bf16(acc[gi][0], ah[1][0], ah[1][1], ah[1][2], ah[1][3], bh0[2], bh0[3]);
                mma_bf16(acc[gi][1], ah[1][0], ah[1][1], ah[1][2], ah[1][3], bh1[2], bh1[3]);
                mma_bf16(acc[gi][0], ah[0][0], ah[0][1], ah[0][2], ah[0][3], bl0[0], bl0[1]);
                mma_bf16(acc[gi][1], ah[0][0], ah[0][1], ah[0][2], ah[0][3], bl1[0], bl1[1]);
                mma_bf16(acc[gi][0], ah[1][0], ah[1][1], ah[1][2], ah[1][3], bl0[2], bl0[3]);
                mma_bf16(acc[gi][1], ah[1][0], ah[1][1], ah[1][2], ah[1][3], bl1[2], bl1[3]);
            }
            // i_n: hh product only
            {
                uint32_t baddr = bufB + b_base + (uint32_t)((2 * 16) * 80);
                uint32_t bh0[4], bh1[4];
                ldsm4(bh0[0], bh0[1], bh0[2], bh0[3], baddr);
                ldsm4(bh1[0], bh1[1], bh1[2], bh1[3], baddr + 640);
                mma_bf16(acc[2][0], ah[0][0], ah[0][1], ah[0][2], ah[0][3], bh0[0], bh0[1]);
                mma_bf16(acc[2][1], ah[0][0], ah[0][1], ah[0][2], ah[0][3], bh1[0], bh1[1]);
                mma_bf16(acc[2][0], ah[1][0], ah[1][1], ah[1][2], ah[1][3], bh0[2], bh0[3]);
                mma_bf16(acc[2][1], ah[1][0], ah[1][1], ah[1][2], ah[1][3], bh1[2], bh1[3]);
            }
        } else {
            uint32_t al[2][4];
#pragma unroll
            for (int kk = 0; kk < 2; kk++)
                ldsm4(al[kk][0], al[kk][1], al[kk][2], al[kk][3],
                      bufB + a_base + kk * 32 + 5120);
            // i_n: hl (ah*bl) + lh (al*bh)
            {
                uint32_t baddr = bufB + b_base + (uint32_t)((2 * 16) * 80);
                uint32_t bh0[4], bl0[4], bh1[4], bl1[4];
                ldsm4(bh0[0], bh0[1], bh0[2], bh0[3], baddr);
                ldsm4(bl0[0], bl0[1], bl0[2], bl0[3], baddr + 5120);
                ldsm4(bh1[0], bh1[1], bh1[2], bh1[3], baddr + 640);
                ldsm4(bl1[0], bl1[1], bl1[2], bl1[3], baddr + 640 + 5120);
                mma_bf16(acc[0][0], ah[0][0], ah[0][1], ah[0][2], ah[0][3], bl0[0], bl0[1]);
                mma_bf16(acc[0][1], ah[0][0], ah[0][1], ah[0][2], ah[0][3], bl1[0], bl1[1]);
                mma_bf16(acc[0][0], ah[1][0], ah[1][1], ah[1][2], ah[1][3], bl0[2], bl0[3]);
                mma_bf16(acc[0][1], ah[1][0], ah[1][1], ah[1][2], ah[1][3], bl1[2], bl1[3]);
                mma_bf16(acc[0][0], al[0][0], al[0][1], al[0][2], al[0][3], bh0[0], bh0[1]);
                mma_bf16(acc[0][1], al[0][0], al[0][1], al[0][2], al[0][3], bh1[0], bh1[1]);
                mma_bf16(acc[0][0], al[1][0], al[1][1], al[1][2], al[1][3], bh0[2], bh0[3]);
                mma_bf16(acc[0][1], al[1][0], al[1][1], al[1][2], al[1][3], bh1[2], bh1[3]);
            }
            // h_n: hh + hl + lh
            {
                uint32_t baddr = bufB + b_base + (uint32_t)((3 * 16) * 80);
                uint32_t bh0[4], bl0[4], bh1[4], bl1[4];
                ldsm4(bh0[0], bh0[1], bh0[2], bh0[3], baddr);
                ldsm4(bl0[0], bl0[1], bl0[2], bl0[3], baddr + 5120);
                ldsm4(bh1[0], bh1[1], bh1[2], bh1[3], baddr + 640);
                ldsm4(bl1[0], bl1[1], bl1[2], bl1[3], baddr + 640 + 5120);
                mma_bf16(acc[1][0], ah[0][0], ah[0][1], ah[0][2], ah[0][3], bh0[0], bh0[1]);
                mma_bf16(acc[1][1], ah[0][0], ah[0][1], ah[0][2], ah[0][3], bh1[0], bh1[1]);
                mma_bf16(acc[1][0], ah[1][0], ah[1][1], ah[1][2], ah[1][3], bh0[2], bh0[3]);
                mma_bf16(acc[1][1], ah[1][0], ah[1][1], ah[1][2], ah[1][3], bh1[2], bh1[3]);
                mma_bf16(acc[1][0], ah[0][0], ah[0][1], ah[0][2], ah[0][3], bl0[0], bl0[1]);
                mma_bf16(acc[1][1], ah[0][0], ah[0][1], ah[0][2], ah[0][3], bl1[0], bl1[1]);
                mma_bf16(acc[1][0], ah[1][0], ah[1][1], ah[1][2], ah[1][3], bl0[2], bl0[3]);
                mma_bf16(acc[1][1], ah[1][0], ah[1][1], ah[1][2], ah[1][3], bl1[2], bl1[3]);
                mma_bf16(acc[1][0], al[0][0], al[0][1], al[0][2], al[0][3], bh0[0], bh0[1]);
                mma_bf16(acc[1][1], al[0][0], al[0][1], al[0][2], al[0][3], bh1[0], bh1[1]);
                mma_bf16(acc[1][0], al[1][0], al[1][1], al[1][2], al[1][3], bh0[2], bh0[3]);
                mma_bf16(acc[1][1], al[1][0], al[1][1], al[1][2], al[1][3], bh1[2], bh1[3]);
            }
        }
    }

    cp_wait<0>();
    __syncthreads();

    // ---- exchange: group 1 -> smem {i_n partial, h_n} -> group 0 ----
    float* xch = (float*)smem;             // 4*32*16 floats = 8 KB (stages dead)
    if (warp_g == 1) {
        int base = (warp_m * 32 + lane) * 16;
#pragma unroll
        for (int a = 0; a < 2; a++)
#pragma unroll
            for (int b = 0; b < 2; b++)
#pragma unroll
                for (int c = 0; c < 4; c++)
                    xch[base + a * 8 + b * 4 + c] = acc[a][b][c];
    }
    __syncthreads();

    if (warp_g == 0) {
        int base = (warp_m * 32 + lane) * 16;
        const __nv_bfloat16* src_hi = g_hs_hi + (size_t)t * B_ * H_;
        const __nv_bfloat16* src_lo = g_hs_lo + (size_t)t * B_ * H_;
        __nv_bfloat16* dst_hi = g_hs_hi + (size_t)(t + 1) * B_ * H_;
        __nv_bfloat16* dst_lo = g_hs_lo + (size_t)(t + 1) * B_ * H_;

#pragma unroll
        for (int nf = 0; nf < 2; nf++)
#pragma unroll
            for (int cc = 0; cc < 2; cc++) {
                int j = j0 + nf * 8 + 2 * t4 + cc;
                float br = b_ih[j]          + b_hh[j];
                float bz = b_ih[H_ + j]     + b_hh[H_ + j];
                float bin = b_ih[2 * H_ + j];
                float bhn = b_hh[2 * H_ + j];
#pragma unroll
                for (int rr = 0; rr < 2; rr++) {
                    int m  = m0 + warp_m * 16 + g + rr * 8;
                    int ci = rr * 2 + cc;
                    float r  = sigm(acc[0][nf][ci] + br);
                    float z  = sigm(acc[1][nf][ci] + bz);
                    float inn = acc[2][nf][ci]                       // i_n hh part
                              + xch[base + 0 * 8 + nf * 4 + ci]      // i_n hl+lh part
                              + bin;
                    float hn  = xch[base + 1 * 8 + nf * 4 + ci] + bhn;
                    float nn = tanh_fast(inn + r * hn);
                    size_t idx = (size_t)m * H_ + j;
                    float hold = __bfloat162float(src_hi[idx]) + __bfloat162float(src_lo[idx]);
                    float hnew = (1.0f - z) * nn + z * hold;
                    __nv_bfloat16 hh = __float2bfloat16(hnew);
                    dst_hi[idx] = hh;
                    dst_lo[idx] = __float2bfloat16(hnew - __bfloat162float(hh));
                }
            }
    }
}

// ---------------------------------------------------------------------------
// Host launcher: graph-capturable.
// ---------------------------------------------------------------------------
extern "C" void kernel_launch(void* const* d_in, const int* in_sizes, int n_in,
                              void* d_out, int out_size) {
    const float* x     = (const float*)d_in[0];
    const float* w1    = (const float*)d_in[1];
    const float* b1    = (const float*)d_in[2];
    const float* w2    = (const float*)d_in[3];
    const float* b2    = (const float*)d_in[4];
    const float* w_ih  = (const float*)d_in[5];
    const float* b_ih  = (const float*)d_in[6];
    const float* w_hh  = (const float*)d_in[7];
    const float* b_hh  = (const float*)d_in[8];
    const float* out_w = (const float*)d_in[9];
    const float* out_b = (const float*)d_in[10];
    float* out = (float*)d_out;

    int T = (out_size - B_ * H_) / (B_ * DOUT_);   // = 256
    if (T > T_) T = T_;

    static bool attr_done = false;
    if (!attr_done) {
        cudaFuncSetAttribute(gru_kernel,
                             cudaFuncAttributeMaxDynamicSharedMemorySize, R_SMEM);
        attr_done = true;
    }

    split_all_kernel<<<(SPLIT_TOTAL + 255) / 256, 256>>>(x, w1, w2, out_w);
    wprep4_kernel<<<4 * H_, 256>>>(w_ih, w_hh);

    // FCN layer 1: t1 = x @ w1^T + b1
    gemm3_kernel<<<dim3(H_ / 64, B_ / 128), 256>>>(0, b1, nullptr, B_, H_, DIN_, 0);
    // FCN layer 2: latent -> d_out latent slice + hs slab 0
    gemm3_kernel<<<dim3(H_ / 64, B_ / 128), 256>>>(
        1, b2, out + (size_t)B_ * T * DOUT_, B_, H_, H_, 1);

    // GRU recurrence (gate-merged + asymmetric precision: 10 product-units)
    for (int t = 0; t < T; t++)
        gru_kernel<<<dim3(H_ / 16, B_ / 64), 256, R_SMEM>>>(t, b_ih, b_hh);

    // Output projection (permuted write)
    gemm3_kernel<<<dim3(DOUT_ / 64, (T * B_) / 128), 256>>>(
        2, out_b, out, T * B_, DOUT_, H_, 2);
}

// round 16
// speedup vs baseline: 1.0388x; 1.0388x over previous
#include <cuda_runtime.h>
#include <cuda_bf16.h>
#include <cstdint>
#include <cstddef>

// Problem constants (shapes fixed by the dataset).
#define B_    256
#define DIN_  512
#define H_    1024
#define DOUT_ 512
#define T_    256

// ---------------------------------------------------------------------------
// Device scratch. hs: T+1 slabs of [B, H] split bf16 (hi+lo).
// GRU weights gate-merged (4 blocks of H rows): 0: W_ir+W_hr, 1: W_iz+W_hz,
// 2: W_in, 3: W_hn.
// ---------------------------------------------------------------------------
__device__ __nv_bfloat16 g_hs_hi[(size_t)(T_ + 1) * B_ * H_];
__device__ __nv_bfloat16 g_hs_lo[(size_t)(T_ + 1) * B_ * H_];
__device__ __nv_bfloat16 g_W4hi[(size_t)4 * H_ * H_];
__device__ __nv_bfloat16 g_W4lo[(size_t)4 * H_ * H_];
__device__ __nv_bfloat16 g_xhi[B_ * DIN_],  g_xlo[B_ * DIN_];
__device__ __nv_bfloat16 g_w1hi[H_ * DIN_], g_w1lo[H_ * DIN_];
__device__ __nv_bfloat16 g_w2hi[H_ * H_],   g_w2lo[H_ * H_];
__device__ __nv_bfloat16 g_t1hi[B_ * H_],   g_t1lo[B_ * H_];
__device__ __nv_bfloat16 g_owhi[DOUT_ * H_], g_owlo[DOUT_ * H_];

// ---------------------------------------------------------------------------
// Split of x, w1, w2, out_w into bf16 hi/lo.
// ---------------------------------------------------------------------------
#define SPLIT_TOTAL 2228224
__global__ void split_all_kernel(const float* __restrict__ x,
                                 const float* __restrict__ w1,
                                 const float* __restrict__ w2,
                                 const float* __restrict__ ow) {
    int i = blockIdx.x * blockDim.x + threadIdx.x;
    if (i >= SPLIT_TOTAL) return;
    const float* src;
    __nv_bfloat16 *hi, *lo;
    int off;
    if (i < 131072)        { src = x;   hi = g_xhi;  lo = g_xlo;  off = i; }
    else if (i < 655360)   { src = w1;  hi = g_w1hi; lo = g_w1lo; off = i - 131072; }
    else if (i < 1703936)  { src = w2;  hi = g_w2hi; lo = g_w2lo; off = i - 655360; }
    else                   { src = ow;  hi = g_owhi; lo = g_owlo; off = i - 1703936; }
    float v = src[off];
    __nv_bfloat16 h = __float2bfloat16(v);
    hi[off] = h;
    lo[off] = __float2bfloat16(v - __bfloat162float(h));
}

// ---------------------------------------------------------------------------
// Gate-merged GRU weight prep: 4H rows, fp32 sums then exact hi/lo split.
// ---------------------------------------------------------------------------
__global__ void wprep4_kernel(const float* __restrict__ wih,
                              const float* __restrict__ whh) {
    int row = blockIdx.x;                  // 0 .. 4H-1
    int gate = row >> 10;
    int j    = row & (H_ - 1);
    for (int i = threadIdx.x; i < H_; i += 256) {
        float v;
        if (gate == 0)      v = wih[(size_t)j * H_ + i]            + whh[(size_t)j * H_ + i];
        else if (gate == 1) v = wih[(size_t)(H_ + j) * H_ + i]     + whh[(size_t)(H_ + j) * H_ + i];
        else if (gate == 2) v = wih[(size_t)(2 * H_ + j) * H_ + i];
        else                v = whh[(size_t)(2 * H_ + j) * H_ + i];
        __nv_bfloat16 h = __float2bfloat16(v);
        size_t idx = (size_t)row * H_ + i;
        g_W4hi[idx] = h;
        g_W4lo[idx] = __float2bfloat16(v - __bfloat162float(h));
    }
}

// ---------------------------------------------------------------------------
// PTX helpers
// ---------------------------------------------------------------------------
__device__ __forceinline__ void mma_bf16(float* c,
                                         uint32_t a0, uint32_t a1, uint32_t a2, uint32_t a3,
                                         uint32_t b0, uint32_t b1) {
    asm volatile(
        "mma.sync.aligned.m16n8k16.row.col.f32.bf16.bf16.f32 "
        "{%0,%1,%2,%3}, {%4,%5,%6,%7}, {%8,%9}, {%0,%1,%2,%3};\n"
        : "+f"(c[0]), "+f"(c[1]), "+f"(c[2]), "+f"(c[3])
        : "r"(a0), "r"(a1), "r"(a2), "r"(a3), "r"(b0), "r"(b1));
}
__device__ __forceinline__ void ldsm4(uint32_t& r0, uint32_t& r1,
                                      uint32_t& r2, uint32_t& r3, uint32_t addr) {
    asm volatile("ldmatrix.sync.aligned.m8n8.x4.shared.b16 {%0,%1,%2,%3}, [%4];\n"
                 : "=r"(r0), "=r"(r1), "=r"(r2), "=r"(r3) : "r"(addr));
}
__device__ __forceinline__ void cp16(uint32_t dst, const void* src) {
    asm volatile("cp.async.cg.shared.global [%0], [%1], 16;\n" :: "r"(dst), "l"(src));
}
__device__ __forceinline__ void cp_commit() {
    asm volatile("cp.async.commit_group;\n");
}
template <int N>
__device__ __forceinline__ void cp_wait() {
    asm volatile("cp.async.wait_group %0;\n" :: "n"(N));
}
__device__ __forceinline__ float sigm(float x) { return 1.0f / (1.0f + __expf(-x)); }
__device__ __forceinline__ float tanh_fast(float x) {
    float a = fabsf(x);
    float e = __expf(-2.0f * a);
    return copysignf((1.0f - e) / (1.0f + e), x);
}

// ---------------------------------------------------------------------------
// Split-bf16 GEMM (proven). BM=128, BN=64, BK=32; 256 threads.
// ---------------------------------------------------------------------------
__global__ __launch_bounds__(256, 2) void gemm3_kernel(
    int which, const float* __restrict__ bias, float* __restrict__ outf,
    int M, int N, int K, int mode)
{
    const __nv_bfloat16 *Ahi, *Alo, *Bhi, *Blo;
    if (which == 0)      { Ahi = g_xhi;  Alo = g_xlo;  Bhi = g_w1hi; Blo = g_w1lo; }
    else if (which == 1) { Ahi = g_t1hi; Alo = g_t1lo; Bhi = g_w2hi; Blo = g_w2lo; }
    else                 { Ahi = g_hs_hi + (size_t)B_ * H_; Alo = g_hs_lo + (size_t)B_ * H_;
                           Bhi = g_owhi; Blo = g_owlo; }
    const uint32_t* A32h = (const uint32_t*)Ahi;
    const uint32_t* A32l = (const uint32_t*)Alo;
    const uint32_t* B32h = (const uint32_t*)Bhi;
    const uint32_t* B32l = (const uint32_t*)Blo;

    __shared__ uint32_t sAh[128 * 20], sAl[128 * 20];
    __shared__ uint32_t sBh[64 * 20],  sBl[64 * 20];

    int tid  = threadIdx.x;
    int lane = tid & 31, warp = tid >> 5;
    int g = lane >> 2, t4 = lane & 3;
    int wm = warp >> 1, wn = warp & 1;
    int m0 = blockIdx.y * 128;
    int n0 = blockIdx.x * 64;
    int K2 = K >> 1;

    float acc[2][4][4];
#pragma unroll
    for (int a = 0; a < 2; a++)
#pragma unroll
        for (int b = 0; b < 4; b++)
#pragma unroll
            for (int c = 0; c < 4; c++) acc[a][b][c] = 0.0f;

    for (int k0 = 0; k0 < K; k0 += 32) {
        __syncthreads();
        int kc = k0 >> 1;
#pragma unroll
        for (int i = 0; i < 8; i++) {
            int e = tid + i * 256;
            int r = e >> 4, c = e & 15;
            size_t gi = (size_t)(m0 + r) * K2 + kc + c;
            sAh[r * 20 + c] = A32h[gi];
            sAl[r * 20 + c] = A32l[gi];
        }
#pragma unroll
        for (int i = 0; i < 4; i++) {
            int e = tid + i * 256;
            int r = e >> 4, c = e & 15;
            size_t gi = (size_t)(n0 + r) * K2 + kc + c;
            sBh[r * 20 + c] = B32h[gi];
            sBl[r * 20 + c] = B32l[gi];
        }
        __syncthreads();

#pragma unroll
        for (int kk = 0; kk < 2; kk++) {
            int base = kk * 8 + t4;
            uint32_t ah[2][4], al[2][4], bh[4][2], bl[4][2];
#pragma unroll
            for (int mf = 0; mf < 2; mf++) {
                int rb = wm * 32 + mf * 16;
                ah[mf][0] = sAh[(rb + g) * 20 + base];
                ah[mf][1] = sAh[(rb + g + 8) * 20 + base];
                ah[mf][2] = sAh[(rb + g) * 20 + base + 4];
                ah[mf][3] = sAh[(rb + g + 8) * 20 + base + 4];
                al[mf][0] = sAl[(rb + g) * 20 + base];
                al[mf][1] = sAl[(rb + g + 8) * 20 + base];
                al[mf][2] = sAl[(rb + g) * 20 + base + 4];
                al[mf][3] = sAl[(rb + g + 8) * 20 + base + 4];
            }
#pragma unroll
            for (int nf = 0; nf < 4; nf++) {
                int nb = wn * 32 + nf * 8 + g;
                bh[nf][0] = sBh[nb * 20 + base];
                bh[nf][1] = sBh[nb * 20 + base + 4];
                bl[nf][0] = sBl[nb * 20 + base];
                bl[nf][1] = sBl[nb * 20 + base + 4];
            }
#pragma unroll
            for (int mf = 0; mf < 2; mf++)
#pragma unroll
                for (int nf = 0; nf < 4; nf++)
                    mma_bf16(acc[mf][nf], ah[mf][0], ah[mf][1], ah[mf][2], ah[mf][3],
                             bh[nf][0], bh[nf][1]);
#pragma unroll
            for (int mf = 0; mf < 2; mf++)
#pragma unroll
                for (int nf = 0; nf < 4; nf++)
                    mma_bf16(acc[mf][nf], ah[mf][0], ah[mf][1], ah[mf][2], ah[mf][3],
                             bl[nf][0], bl[nf][1]);
#pragma unroll
            for (int mf = 0; mf < 2; mf++)
#pragma unroll
                for (int nf = 0; nf < 4; nf++)
                    mma_bf16(acc[mf][nf], al[mf][0], al[mf][1], al[mf][2], al[mf][3],
                             bh[nf][0], bh[nf][1]);
        }
    }

#pragma unroll
    for (int mf = 0; mf < 2; mf++)
#pragma unroll
        for (int nf = 0; nf < 4; nf++)
#pragma unroll
            for (int rr = 0; rr < 2; rr++)
#pragma unroll
                for (int cc = 0; cc < 2; cc++) {
                    int row = m0 + wm * 32 + mf * 16 + g + rr * 8;
                    int col = n0 + wn * 32 + nf * 8 + 2 * t4 + cc;
                    float v = acc[mf][nf][rr * 2 + cc] + bias[col];
                    if (mode == 0) {
                        __nv_bfloat16 h = __float2bfloat16(v);
                        g_t1hi[(size_t)row * N + col] = h;
                        g_t1lo[(size_t)row * N + col] =
                            __float2bfloat16(v - __bfloat162float(h));
                    } else if (mode == 1) {
                        outf[(size_t)row * N + col] = v;
                        __nv_bfloat16 h = __float2bfloat16(v);
                        g_hs_hi[(size_t)row * N + col] = h;
                        g_hs_lo[(size_t)row * N + col] =
                            __float2bfloat16(v - __bfloat162float(h));
                    } else {
                        int t = row >> 8;               // row = t*B + b
                        int b = row & 255;
                        int Trt = M >> 8;
                        outf[(size_t)b * Trt * N + (size_t)t * N + col] = v;
                    }
                }
}

// ---------------------------------------------------------------------------
// Fused GRU step — gate-merged + asymmetric precision, UNIFORM code.
// BM=64, BN=16, grid (64, 4) = 256 CTAs, 2 CTAs/SM, 4-stage cp.async.
// Both warp groups execute the identical 5-unit schedule; only register-held
// addresses differ:
//   unit:      0        1        2        3        4
//   A-frag:    ah       aY       ah       ah       aY      (aY = hi or lo by addr)
//   group0 B:  g0-hi    g0-lo    g1-hi    g1-lo    g2-hi   (r hh,hl; z hh,hl; i_n hh)
//   group1 B:  g2-lo    g2-hi    g3-hi    g3-lo    g3-hi   (i_n hl,lh; h_n hh,hl,lh)
//   acc:       0        0        1        1        2
// group1 epilogue: i_n partial = acc0, h_n = acc1 + acc2.
// r/z drop the lo*hi product (validated: rel_err 7.7e-5 in r15).
// ---------------------------------------------------------------------------
#define STAGES  4
#define R_BUF   (256 * 20)                 // u32 per stage (5120)
#define R_SMEM  (STAGES * R_BUF * 4)       // 81920 bytes dynamic

__global__ __launch_bounds__(256, 2) void gru_kernel(
    int t, const float* __restrict__ b_ih, const float* __restrict__ b_hh)
{
    extern __shared__ uint32_t smem[];

    int tid  = threadIdx.x;
    int lane = tid & 31, warp = tid >> 5;
    int g = lane >> 2, t4 = lane & 3;
    int warp_m = warp & 3, warp_g = warp >> 2;
    int m0 = blockIdx.y * 64;
    int j0 = blockIdx.x * 16;
    uint32_t sb = (uint32_t)__cvta_generic_to_shared(smem);

    // ---- per-thread load plan: 4 x 16B chunks per k32 tile ----
    const uint4* srcp[4];
    uint32_t     soff[4];
#pragma unroll
    for (int i = 0; i < 4; i++) {
        int c = tid + i * 256;             // 0..1023
        if (c < 512) {                     // A (h): hi then lo, 64 rows x 4 chunks
            int half = c >> 8, rem = c & 255;
            int row = rem >> 2, ch = rem & 3;
            const __nv_bfloat16* base =
                (half ? g_hs_lo : g_hs_hi) + (size_t)t * B_ * H_;
            srcp[i] = (const uint4*)base + (size_t)(m0 + row) * 128 + ch;
            soff[i] = (uint32_t)(half * 1280 + row * 20 + ch * 4) * 4;
        } else {                           // W4: hi then lo, 64 rows x 4 chunks
            int c2 = c - 512;
            int half = c2 >> 8, rem = c2 & 255;
            int row = rem >> 2, ch = rem & 3;
            int gate = row >> 4, rj = row & 15;
            const __nv_bfloat16* base = half ? g_W4lo : g_W4hi;
            srcp[i] = (const uint4*)base + (size_t)(gate * H_ + j0 + rj) * 128 + ch;
            soff[i] = (uint32_t)(2560 + half * 1280 + row * 20 + ch * 4) * 4;
        }
    }

    // LDSM address bases (byte offsets within a stage)
    int rb = warp_m * 16;
    uint32_t a_base = (uint32_t)((rb + (lane & 15)) * 80 + (lane >> 4) * 16);
    int q = lane >> 3;
    uint32_t b_base = (uint32_t)(10240 + (lane & 7) * 80 + (q >> 1) * 32 + (q & 1) * 16);

    // Per-warp unit tables (register scalars; uniform code thereafter).
    // Gate block g occupies +g*1280 bytes in the B-hi region; B-lo at +5120.
    uint32_t boff0, boff1, boff2, boff3, boff4;
    if (warp_g == 0) {
        boff0 = b_base + 0;               // r  hh
        boff1 = b_base + 5120;            // r  hl
        boff2 = b_base + 1280;            // z  hh
        boff3 = b_base + 1280 + 5120;     // z  hl
        boff4 = b_base + 2560;            // i_n hh
    } else {
        boff0 = b_base + 2560 + 5120;     // i_n hl
        boff1 = b_base + 2560;            // i_n lh (A = lo)
        boff2 = b_base + 3840;            // h_n hh
        boff3 = b_base + 3840 + 5120;     // h_n hl
        boff4 = b_base + 3840;            // h_n lh (A = lo)
    }
    uint32_t aY_off = a_base + (warp_g ? 5120u : 0u);

    // acc[0], acc[1], acc[2] as per the unit table.
    float acc[3][2][4];
#pragma unroll
    for (int a = 0; a < 3; a++)
#pragma unroll
        for (int b = 0; b < 2; b++)
#pragma unroll
            for (int c = 0; c < 4; c++) acc[a][b][c] = 0.0f;

    auto load_tile = [&](int kt) {
        if (kt < 32) {
            uint32_t sbase = sb + (uint32_t)(kt & (STAGES - 1)) * (R_BUF * 4);
#pragma unroll
            for (int i = 0; i < 4; i++)
                cp16(sbase + soff[i], srcp[i] + kt * 4);
        }
        cp_commit();
    };

    load_tile(0);
    load_tile(1);
    load_tile(2);

    for (int kt = 0; kt < 32; kt++) {
        cp_wait<2>();
        __syncthreads();
        load_tile(kt + 3);

        uint32_t bufB = sb + (uint32_t)(kt & (STAGES - 1)) * (R_BUF * 4);

        uint32_t ah[2][4], aY[2][4];
#pragma unroll
        for (int kk = 0; kk < 2; kk++) {
            ldsm4(ah[kk][0], ah[kk][1], ah[kk][2], ah[kk][3],
                  bufB + a_base + kk * 32);
            ldsm4(aY[kk][0], aY[kk][1], aY[kk][2], aY[kk][3],
                  bufB + aY_off + kk * 32);
        }

#define GRU_UNIT(BOFF, AARR, ACCI)                                              \
        {                                                                       \
            uint32_t b0[4], b1[4];                                              \
            ldsm4(b0[0], b0[1], b0[2], b0[3], bufB + (BOFF));                   \
            ldsm4(b1[0], b1[1], b1[2], b1[3], bufB + (BOFF) + 640);             \
            mma_bf16(acc[ACCI][0], AARR[0][0], AARR[0][1], AARR[0][2],          \
                     AARR[0][3], b0[0], b0[1]);                                 \
            mma_bf16(acc[ACCI][1], AARR[0][0], AARR[0][1], AARR[0][2],          \
                     AARR[0][3], b1[0], b1[1]);                                 \
            mma_bf16(acc[ACCI][0], AARR[1][0], AARR[1][1], AARR[1][2],          \
                     AARR[1][3], b0[2], b0[3]);                                 \
            mma_bf16(acc[ACCI][1], AARR[1][0], AARR[1][1], AARR[1][2],          \
                     AARR[1][3], b1[2], b1[3]);                                 \
        }

        GRU_UNIT(boff0, ah, 0)
        GRU_UNIT(boff1, aY, 0)
        GRU_UNIT(boff2, ah, 1)
        GRU_UNIT(boff3, ah, 1)
        GRU_UNIT(boff4, aY, 2)
#undef GRU_UNIT
    }

    cp_wait<0>();
    __syncthreads();

    // ---- exchange: group1 -> smem {i_n partial, h_n} -> group0 ----
    float* xch = (float*)smem;             // 4*32*16 floats = 8 KB (stages dead)
    if (warp_g == 1) {
        int base = (warp_m * 32 + lane) * 16;
#pragma unroll
        for (int b = 0; b < 2; b++)
#pragma unroll
            for (int c = 0; c < 4; c++) {
                xch[base + 0 * 8 + b * 4 + c] = acc[0][b][c];                 // i_n hl+lh
                xch[base + 1 * 8 + b * 4 + c] = acc[1][b][c] + acc[2][b][c];  // h_n full
            }
    }
    __syncthreads();

    if (warp_g == 0) {
        int base = (warp_m * 32 + lane) * 16;
        const __nv_bfloat16* src_hi = g_hs_hi + (size_t)t * B_ * H_;
        const __nv_bfloat16* src_lo = g_hs_lo + (size_t)t * B_ * H_;
        __nv_bfloat16* dst_hi = g_hs_hi + (size_t)(t + 1) * B_ * H_;
        __nv_bfloat16* dst_lo = g_hs_lo + (size_t)(t + 1) * B_ * H_;

#pragma unroll
        for (int nf = 0; nf < 2; nf++)
#pragma unroll
            for (int cc = 0; cc < 2; cc++) {
                int j = j0 + nf * 8 + 2 * t4 + cc;
                float br  = b_ih[j]      + b_hh[j];
                float bz  = b_ih[H_ + j] + b_hh[H_ + j];
                float bin = b_ih[2 * H_ + j];
                float bhn = b_hh[2 * H_ + j];
#pragma unroll
                for (int rr = 0; rr < 2; rr++) {
                    int m  = m0 + warp_m * 16 + g + rr * 8;
                    int ci = rr * 2 + cc;
                    float r  = sigm(acc[0][nf][ci] + br);
                    float z  = sigm(acc[1][nf][ci] + bz);
                    float inn = acc[2][nf][ci]                     // i_n hh
                              + xch[base + 0 * 8 + nf * 4 + ci]    // i_n hl+lh
                              + bin;
                    float hn  = xch[base + 1 * 8 + nf * 4 + ci] + bhn;
                    float nn = tanh_fast(inn + r * hn);
                    size_t idx = (size_t)m * H_ + j;
                    float hold = __bfloat162float(src_hi[idx]) + __bfloat162float(src_lo[idx]);
                    float hnew = (1.0f - z) * nn + z * hold;
                    __nv_bfloat16 hh = __float2bfloat16(hnew);
                    dst_hi[idx] = hh;
                    dst_lo[idx] = __float2bfloat16(hnew - __bfloat162float(hh));
                }
            }
    }
}

// ---------------------------------------------------------------------------
// Host launcher: graph-capturable.
// ---------------------------------------------------------------------------
extern "C" void kernel_launch(void* const* d_in, const int* in_sizes, int n_in,
                              void* d_out, int out_size) {
    const float* x     = (const float*)d_in[0];
    const float* w1    = (const float*)d_in[1];
    const float* b1    = (const float*)d_in[2];
    const float* w2    = (const float*)d_in[3];
    const float* b2    = (const float*)d_in[4];
    const float* w_ih  = (const float*)d_in[5];
    const float* b_ih  = (const float*)d_in[6];
    const float* w_hh  = (const float*)d_in[7];
    const float* b_hh  = (const float*)d_in[8];
    const float* out_w = (const float*)d_in[9];
    const float* out_b = (const float*)d_in[10];
    float* out = (float*)d_out;

    int T = (out_size - B_ * H_) / (B_ * DOUT_);   // = 256
    if (T > T_) T = T_;

    static bool attr_done = false;
    if (!attr_done) {
        cudaFuncSetAttribute(gru_kernel,
                             cudaFuncAttributeMaxDynamicSharedMemorySize, R_SMEM);
        attr_done = true;
    }

    split_all_kernel<<<(SPLIT_TOTAL + 255) / 256, 256>>>(x, w1, w2, out_w);
    wprep4_kernel<<<4 * H_, 256>>>(w_ih, w_hh);

    // FCN layer 1: t1 = x @ w1^T + b1
    gemm3_kernel<<<dim3(H_ / 64, B_ / 128), 256>>>(0, b1, nullptr, B_, H_, DIN_, 0);
    // FCN layer 2: latent -> d_out latent slice + hs slab 0
    gemm3_kernel<<<dim3(H_ / 64, B_ / 128), 256>>>(
        1, b2, out + (size_t)B_ * T * DOUT_, B_, H_, H_, 1);

    // GRU recurrence (gate-merged + asymmetric precision, uniform code)
    for (int t = 0; t < T; t++)
        gru_kernel<<<dim3(H_ / 16, B_ / 64), 256, R_SMEM>>>(t, b_ih, b_hh);

    // Output projection (permuted write)
    gemm3_kernel<<<dim3(DOUT_ / 64, (T * B_) / 128), 256>>>(
        2, out_b, out, T * B_, DOUT_, H_, 2);
}

// round 17
// speedup vs baseline: 1.0970x; 1.0561x over previous
#include <cuda_runtime.h>
#include <cuda_bf16.h>
#include <cstdint>
#include <cstddef>

// Problem constants (shapes fixed by the dataset).
#define B_    256
#define DIN_  512
#define H_    1024
#define DOUT_ 512
#define T_    256

// ---------------------------------------------------------------------------
// Device scratch. hs: T+1 slabs of [B, H] split bf16 (hi+lo).
// GRU weights gate-merged (4 blocks of H rows): 0: W_ir+W_hr, 1: W_iz+W_hz,
// 2: W_in, 3: W_hn.
// ---------------------------------------------------------------------------
__device__ __nv_bfloat16 g_hs_hi[(size_t)(T_ + 1) * B_ * H_];
__device__ __nv_bfloat16 g_hs_lo[(size_t)(T_ + 1) * B_ * H_];
__device__ __nv_bfloat16 g_W4hi[(size_t)4 * H_ * H_];
__device__ __nv_bfloat16 g_W4lo[(size_t)4 * H_ * H_];
__device__ __nv_bfloat16 g_xhi[B_ * DIN_],  g_xlo[B_ * DIN_];
__device__ __nv_bfloat16 g_w1hi[H_ * DIN_], g_w1lo[H_ * DIN_];
__device__ __nv_bfloat16 g_w2hi[H_ * H_],   g_w2lo[H_ * H_];
__device__ __nv_bfloat16 g_t1hi[B_ * H_],   g_t1lo[B_ * H_];
__device__ __nv_bfloat16 g_owhi[DOUT_ * H_], g_owlo[DOUT_ * H_];

// ---------------------------------------------------------------------------
// Split of x, w1, w2, out_w into bf16 hi/lo.
// ---------------------------------------------------------------------------
#define SPLIT_TOTAL 2228224
__global__ void split_all_kernel(const float* __restrict__ x,
                                 const float* __restrict__ w1,
                                 const float* __restrict__ w2,
                                 const float* __restrict__ ow) {
    int i = blockIdx.x * blockDim.x + threadIdx.x;
    if (i >= SPLIT_TOTAL) return;
    const float* src;
    __nv_bfloat16 *hi, *lo;
    int off;
    if (i < 131072)        { src = x;   hi = g_xhi;  lo = g_xlo;  off = i; }
    else if (i < 655360)   { src = w1;  hi = g_w1hi; lo = g_w1lo; off = i - 131072; }
    else if (i < 1703936)  { src = w2;  hi = g_w2hi; lo = g_w2lo; off = i - 655360; }
    else                   { src = ow;  hi = g_owhi; lo = g_owlo; off = i - 1703936; }
    float v = src[off];
    __nv_bfloat16 h = __float2bfloat16(v);
    hi[off] = h;
    lo[off] = __float2bfloat16(v - __bfloat162float(h));
}

// ---------------------------------------------------------------------------
// Gate-merged GRU weight prep: 4H rows, fp32 sums then exact hi/lo split.
// ---------------------------------------------------------------------------
__global__ void wprep4_kernel(const float* __restrict__ wih,
                              const float* __restrict__ whh) {
    int row = blockIdx.x;                  // 0 .. 4H-1
    int gate = row >> 10;
    int j    = row & (H_ - 1);
    for (int i = threadIdx.x; i < H_; i += 256) {
        float v;
        if (gate == 0)      v = wih[(size_t)j * H_ + i]            + whh[(size_t)j * H_ + i];
        else if (gate == 1) v = wih[(size_t)(H_ + j) * H_ + i]     + whh[(size_t)(H_ + j) * H_ + i];
        else if (gate == 2) v = wih[(size_t)(2 * H_ + j) * H_ + i];
        else                v = whh[(size_t)(2 * H_ + j) * H_ + i];
        __nv_bfloat16 h = __float2bfloat16(v);
        size_t idx = (size_t)row * H_ + i;
        g_W4hi[idx] = h;
        g_W4lo[idx] = __float2bfloat16(v - __bfloat162float(h));
    }
}

// ---------------------------------------------------------------------------
// PTX helpers
// ---------------------------------------------------------------------------
__device__ __forceinline__ void mma_bf16(float* c,
                                         uint32_t a0, uint32_t a1, uint32_t a2, uint32_t a3,
                                         uint32_t b0, uint32_t b1) {
    asm volatile(
        "mma.sync.aligned.m16n8k16.row.col.f32.bf16.bf16.f32 "
        "{%0,%1,%2,%3}, {%4,%5,%6,%7}, {%8,%9}, {%0,%1,%2,%3};\n"
        : "+f"(c[0]), "+f"(c[1]), "+f"(c[2]), "+f"(c[3])
        : "r"(a0), "r"(a1), "r"(a2), "r"(a3), "r"(b0), "r"(b1));
}
__device__ __forceinline__ void ldsm4(uint32_t& r0, uint32_t& r1,
                                      uint32_t& r2, uint32_t& r3, uint32_t addr) {
    asm volatile("ldmatrix.sync.aligned.m8n8.x4.shared.b16 {%0,%1,%2,%3}, [%4];\n"
                 : "=r"(r0), "=r"(r1), "=r"(r2), "=r"(r3) : "r"(addr));
}
__device__ __forceinline__ void cp16(uint32_t dst, const void* src) {
    asm volatile("cp.async.cg.shared.global [%0], [%1], 16;\n" :: "r"(dst), "l"(src));
}
__device__ __forceinline__ void cp_commit() {
    asm volatile("cp.async.commit_group;\n");
}
template <int N>
__device__ __forceinline__ void cp_wait() {
    asm volatile("cp.async.wait_group %0;\n" :: "n"(N));
}
__device__ __forceinline__ float sigm(float x) { return 1.0f / (1.0f + __expf(-x)); }
__device__ __forceinline__ float tanh_fast(float x) {
    float a = fabsf(x);
    float e = __expf(-2.0f * a);
    return copysignf((1.0f - e) / (1.0f + e), x);
}

// ---------------------------------------------------------------------------
// Split-bf16 GEMM (proven). BM=128, BN=64, BK=32; 256 threads.
// ---------------------------------------------------------------------------
__global__ __launch_bounds__(256, 2) void gemm3_kernel(
    int which, const float* __restrict__ bias, float* __restrict__ outf,
    int M, int N, int K, int mode)
{
    const __nv_bfloat16 *Ahi, *Alo, *Bhi, *Blo;
    if (which == 0)      { Ahi = g_xhi;  Alo = g_xlo;  Bhi = g_w1hi; Blo = g_w1lo; }
    else if (which == 1) { Ahi = g_t1hi; Alo = g_t1lo; Bhi = g_w2hi; Blo = g_w2lo; }
    else                 { Ahi = g_hs_hi + (size_t)B_ * H_; Alo = g_hs_lo + (size_t)B_ * H_;
                           Bhi = g_owhi; Blo = g_owlo; }
    const uint32_t* A32h = (const uint32_t*)Ahi;
    const uint32_t* A32l = (const uint32_t*)Alo;
    const uint32_t* B32h = (const uint32_t*)Bhi;
    const uint32_t* B32l = (const uint32_t*)Blo;

    __shared__ uint32_t sAh[128 * 20], sAl[128 * 20];
    __shared__ uint32_t sBh[64 * 20],  sBl[64 * 20];

    int tid  = threadIdx.x;
    int lane = tid & 31, warp = tid >> 5;
    int g = lane >> 2, t4 = lane & 3;
    int wm = warp >> 1, wn = warp & 1;
    int m0 = blockIdx.y * 128;
    int n0 = blockIdx.x * 64;
    int K2 = K >> 1;

    float acc[2][4][4];
#pragma unroll
    for (int a = 0; a < 2; a++)
#pragma unroll
        for (int b = 0; b < 4; b++)
#pragma unroll
            for (int c = 0; c < 4; c++) acc[a][b][c] = 0.0f;

    for (int k0 = 0; k0 < K; k0 += 32) {
        __syncthreads();
        int kc = k0 >> 1;
#pragma unroll
        for (int i = 0; i < 8; i++) {
            int e = tid + i * 256;
            int r = e >> 4, c = e & 15;
            size_t gi = (size_t)(m0 + r) * K2 + kc + c;
            sAh[r * 20 + c] = A32h[gi];
            sAl[r * 20 + c] = A32l[gi];
        }
#pragma unroll
        for (int i = 0; i < 4; i++) {
            int e = tid + i * 256;
            int r = e >> 4, c = e & 15;
            size_t gi = (size_t)(n0 + r) * K2 + kc + c;
            sBh[r * 20 + c] = B32h[gi];
            sBl[r * 20 + c] = B32l[gi];
        }
        __syncthreads();

#pragma unroll
        for (int kk = 0; kk < 2; kk++) {
            int base = kk * 8 + t4;
            uint32_t ah[2][4], al[2][4], bh[4][2], bl[4][2];
#pragma unroll
            for (int mf = 0; mf < 2; mf++) {
                int rb = wm * 32 + mf * 16;
                ah[mf][0] = sAh[(rb + g) * 20 + base];
                ah[mf][1] = sAh[(rb + g + 8) * 20 + base];
                ah[mf][2] = sAh[(rb + g) * 20 + base + 4];
                ah[mf][3] = sAh[(rb + g + 8) * 20 + base + 4];
                al[mf][0] = sAl[(rb + g) * 20 + base];
                al[mf][1] = sAl[(rb + g + 8) * 20 + base];
                al[mf][2] = sAl[(rb + g) * 20 + base + 4];
                al[mf][3] = sAl[(rb + g + 8) * 20 + base + 4];
            }
#pragma unroll
            for (int nf = 0; nf < 4; nf++) {
                int nb = wn * 32 + nf * 8 + g;
                bh[nf][0] = sBh[nb * 20 + base];
                bh[nf][1] = sBh[nb * 20 + base + 4];
                bl[nf][0] = sBl[nb * 20 + base];
                bl[nf][1] = sBl[nb * 20 + base + 4];
            }
#pragma unroll
            for (int mf = 0; mf < 2; mf++)
#pragma unroll
                for (int nf = 0; nf < 4; nf++)
                    mma_bf16(acc[mf][nf], ah[mf][0], ah[mf][1], ah[mf][2], ah[mf][3],
                             bh[nf][0], bh[nf][1]);
#pragma unroll
            for (int mf = 0; mf < 2; mf++)
#pragma unroll
                for (int nf = 0; nf < 4; nf++)
                    mma_bf16(acc[mf][nf], ah[mf][0], ah[mf][1], ah[mf][2], ah[mf][3],
                             bl[nf][0], bl[nf][1]);
#pragma unroll
            for (int mf = 0; mf < 2; mf++)
#pragma unroll
                for (int nf = 0; nf < 4; nf++)
                    mma_bf16(acc[mf][nf], al[mf][0], al[mf][1], al[mf][2], al[mf][3],
                             bh[nf][0], bh[nf][1]);
        }
    }

#pragma unroll
    for (int mf = 0; mf < 2; mf++)
#pragma unroll
        for (int nf = 0; nf < 4; nf++)
#pragma unroll
            for (int rr = 0; rr < 2; rr++)
#pragma unroll
                for (int cc = 0; cc < 2; cc++) {
                    int row = m0 + wm * 32 + mf * 16 + g + rr * 8;
                    int col = n0 + wn * 32 + nf * 8 + 2 * t4 + cc;
                    float v = acc[mf][nf][rr * 2 + cc] + bias[col];
                    if (mode == 0) {
                        __nv_bfloat16 h = __float2bfloat16(v);
                        g_t1hi[(size_t)row * N + col] = h;
                        g_t1lo[(size_t)row * N + col] =
                            __float2bfloat16(v - __bfloat162float(h));
                    } else if (mode == 1) {
                        outf[(size_t)row * N + col] = v;
                        __nv_bfloat16 h = __float2bfloat16(v);
                        g_hs_hi[(size_t)row * N + col] = h;
                        g_hs_lo[(size_t)row * N + col] =
                            __float2bfloat16(v - __bfloat162float(h));
                    } else {
                        int t = row >> 8;               // row = t*B + b
                        int b = row & 255;
                        int Trt = M >> 8;
                        outf[(size_t)b * Trt * N + (size_t)t * N + col] = v;
                    }
                }
}

// ---------------------------------------------------------------------------
// Fused GRU step — gate-merged, r14 math, BK=64 (16 K-tiles), 3-stage
// cp.async. BM=64, BN=16, grid (64, 4) = 256 CTAs, 2 CTAs/SM.
// 8 warps: warp_m = warp&3 (16 rows), warp_g = warp>>2 (gates 0,1 / 2,3).
// Stage layout (u32, row stride 36 = 128B data + 16B pad, conflict-free):
//   Ah[64*36 @0] Al[@2304] Bh[@4608] Bl[@6912] = 9216 u32 = 36864 B.
// Per BK=64 tile the compute body is exactly two r14 k32 sub-iterations
// (bit-identical accumulation order); barriers per step drop 32 -> 16.
// ---------------------------------------------------------------------------
#define R_STG_U32 9216
#define R_SMEM    (3 * R_STG_U32 * 4)      // 110592 bytes dynamic

__global__ __launch_bounds__(256, 2) void gru_kernel(
    int t, const float* __restrict__ b_ih, const float* __restrict__ b_hh)
{
    extern __shared__ uint32_t smem[];

    int tid  = threadIdx.x;
    int lane = tid & 31, warp = tid >> 5;
    int g = lane >> 2, t4 = lane & 3;
    int warp_m = warp & 3, warp_g = warp >> 2;
    int m0 = blockIdx.y * 64;
    int j0 = blockIdx.x * 16;
    uint32_t sb = (uint32_t)__cvta_generic_to_shared(smem);

    // ---- per-thread chunk offsets (u4 units, within each array) ----
    // chunk id c = tid + i*256; rem = c & 511 is tid (even i) or tid+256 (odd).
    uint32_t ga0, ga1, gb0, gb1;
    {
        int r0 = tid >> 3,        c0 = tid & 7;
        int r1 = (tid + 256) >> 3, c1 = tid & 7;
        ga0 = (uint32_t)(t * 32768 + (m0 + r0) * 128 + c0);
        ga1 = (uint32_t)(t * 32768 + (m0 + r1) * 128 + c1);
        int gt0 = r0 >> 4, rj0 = r0 & 15;
        int gt1 = r1 >> 4, rj1 = r1 & 15;
        gb0 = (uint32_t)((gt0 * 1024 + j0 + rj0) * 128 + c0);
        gb1 = (uint32_t)((gt1 * 1024 + j0 + rj1) * 128 + c1);
    }

    // LDSM address bases (byte offsets within a stage); lo regions at +9216B.
    int rb = warp_m * 16;
    uint32_t a_base = (uint32_t)((rb + (lane & 15)) * 144 + (lane >> 4) * 16);
    int q = lane >> 3;
    uint32_t b_base = (uint32_t)(18432 + (lane & 7) * 144 + (q >> 1) * 32 + (q & 1) * 16);

    float acc[2][2][4];
#pragma unroll
    for (int a = 0; a < 2; a++)
#pragma unroll
        for (int b = 0; b < 2; b++)
#pragma unroll
            for (int c = 0; c < 4; c++) acc[a][b][c] = 0.0f;

    // ---- async loader: tile kt -> stage kt % 3; 8 x 16B chunks / thread ----
    auto load_tile = [&](int kt) {
        if (kt < 16) {
            uint32_t sbase = sb + (uint32_t)(kt % 3) * (R_STG_U32 * 4);
            uint32_t o = (uint32_t)kt * 8;
#pragma unroll
            for (int i = 0; i < 8; i++) {
                int c = tid + i * 256;
                uint32_t soff = (uint32_t)(((c >> 9) * 2304
                                 + ((c & 511) >> 3) * 36 + (c & 7) * 4) * 4);
                const uint4* bp;
                uint32_t go;
                if (i < 2)      { bp = (const uint4*)g_hs_hi; go = (i == 0) ? ga0 : ga1; }
                else if (i < 4) { bp = (const uint4*)g_hs_lo; go = (i == 2) ? ga0 : ga1; }
                else if (i < 6) { bp = (const uint4*)g_W4hi;  go = (i == 4) ? gb0 : gb1; }
                else            { bp = (const uint4*)g_W4lo;  go = (i == 6) ? gb0 : gb1; }
                cp16(sbase + soff, bp + go + o);
            }
        }
        cp_commit();
    };

    load_tile(0);
    load_tile(1);

    for (int kt = 0; kt < 16; kt++) {
        cp_wait<1>();                      // tile kt resident
        __syncthreads();                   // stage (kt+2)%3 free to overwrite
        load_tile(kt + 2);

        uint32_t bufB = sb + (uint32_t)(kt % 3) * (R_STG_U32 * 4);

#pragma unroll
        for (int kp = 0; kp < 2; kp++) {   // two k32 halves of the k64 tile
            uint32_t ah[2][4], al[2][4];
#pragma unroll
            for (int kk = 0; kk < 2; kk++) {
                uint32_t aaddr = bufB + a_base + kp * 64 + kk * 32;
                ldsm4(ah[kk][0], ah[kk][1], ah[kk][2], ah[kk][3], aaddr);
                ldsm4(al[kk][0], al[kk][1], al[kk][2], al[kk][3], aaddr + 9216);
            }

#pragma unroll
            for (int gi = 0; gi < 2; gi++) {
                int gate = warp_g * 2 + gi;
                uint32_t baddr = bufB + b_base + (uint32_t)(gate * 2304) + kp * 64;
                uint32_t bh0[4], bl0[4], bh1[4], bl1[4];
                ldsm4(bh0[0], bh0[1], bh0[2], bh0[3], baddr);
                ldsm4(bl0[0], bl0[1], bl0[2], bl0[3], baddr + 9216);
                ldsm4(bh1[0], bh1[1], bh1[2], bh1[3], baddr + 1152);
                ldsm4(bl1[0], bl1[1], bl1[2], bl1[3], baddr + 1152 + 9216);
                mma_bf16(acc[gi][0], ah[0][0], ah[0][1], ah[0][2], ah[0][3], bh0[0], bh0[1]);
                mma_bf16(acc[gi][1], ah[0][0], ah[0][1], ah[0][2], ah[0][3], bh1[0], bh1[1]);
                mma_bf16(acc[gi][0], ah[1][0], ah[1][1], ah[1][2], ah[1][3], bh0[2], bh0[3]);
                mma_bf16(acc[gi][1], ah[1][0], ah[1][1], ah[1][2], ah[1][3], bh1[2], bh1[3]);
                mma_bf16(acc[gi][0], ah[0][0], ah[0][1], ah[0][2], ah[0][3], bl0[0], bl0[1]);
                mma_bf16(acc[gi][1], ah[0][0], ah[0][1], ah[0][2], ah[0][3], bl1[0], bl1[1]);
                mma_bf16(acc[gi][0], ah[1][0], ah[1][1], ah[1][2], ah[1][3], bl0[2], bl0[3]);
                mma_bf16(acc[gi][1], ah[1][0], ah[1][1], ah[1][2], ah[1][3], bl1[2], bl1[3]);
                mma_bf16(acc[gi][0], al[0][0], al[0][1], al[0][2], al[0][3], bh0[0], bh0[1]);
                mma_bf16(acc[gi][1], al[0][0], al[0][1], al[0][2], al[0][3], bh1[0], bh1[1]);
                mma_bf16(acc[gi][0], al[1][0], al[1][1], al[1][2], al[1][3], bh0[2], bh0[3]);
                mma_bf16(acc[gi][1], al[1][0], al[1][1], al[1][2], al[1][3], bh1[2], bh1[3]);
            }
        }
    }

    cp_wait<0>();
    __syncthreads();

    // ---- gate exchange: n-gate warps (group 1) -> smem -> r/z warps ----
    float* xch = (float*)smem;             // 4*32*16 floats = 8 KB (stages dead)
    if (warp_g == 1) {
        int base = (warp_m * 32 + lane) * 16;
#pragma unroll
        for (int a = 0; a < 2; a++)
#pragma unroll
            for (int b = 0; b < 2; b++)
#pragma unroll
                for (int c = 0; c < 4; c++)
                    xch[base + a * 8 + b * 4 + c] = acc[a][b][c];
    }
    __syncthreads();

    if (warp_g == 0) {
        int base = (warp_m * 32 + lane) * 16;
        const __nv_bfloat16* src_hi = g_hs_hi + (size_t)t * B_ * H_;
        const __nv_bfloat16* src_lo = g_hs_lo + (size_t)t * B_ * H_;
        __nv_bfloat16* dst_hi = g_hs_hi + (size_t)(t + 1) * B_ * H_;
        __nv_bfloat16* dst_lo = g_hs_lo + (size_t)(t + 1) * B_ * H_;

#pragma unroll
        for (int nf = 0; nf < 2; nf++)
#pragma unroll
            for (int cc = 0; cc < 2; cc++) {
                int j = j0 + nf * 8 + 2 * t4 + cc;
                float br  = b_ih[j]      + b_hh[j];
                float bz  = b_ih[H_ + j] + b_hh[H_ + j];
                float bin = b_ih[2 * H_ + j];
                float bhn = b_hh[2 * H_ + j];
#pragma unroll
                for (int rr = 0; rr < 2; rr++) {
                    int m  = m0 + warp_m * 16 + g + rr * 8;
                    int ci = rr * 2 + cc;
                    float r  = sigm(acc[0][nf][ci] + br);
                    float z  = sigm(acc[1][nf][ci] + bz);
                    float inn = xch[base + 0 * 8 + nf * 4 + ci] + bin;   // i_n
                    float hn  = xch[base + 1 * 8 + nf * 4 + ci] + bhn;   // h_n
                    float nn = tanh_fast(inn + r * hn);
                    size_t idx = (size_t)m * H_ + j;
                    float hold = __bfloat162float(src_hi[idx]) + __bfloat162float(src_lo[idx]);
                    float hnew = (1.0f - z) * nn + z * hold;
                    __nv_bfloat16 hh = __float2bfloat16(hnew);
                    dst_hi[idx] = hh;
                    dst_lo[idx] = __float2bfloat16(hnew - __bfloat162float(hh));
                }
            }
    }
}

// ---------------------------------------------------------------------------
// Host launcher: graph-capturable.
// ---------------------------------------------------------------------------
extern "C" void kernel_launch(void* const* d_in, const int* in_sizes, int n_in,
                              void* d_out, int out_size) {
    const float* x     = (const float*)d_in[0];
    const float* w1    = (const float*)d_in[1];
    const float* b1    = (const float*)d_in[2];
    const float* w2    = (const float*)d_in[3];
    const float* b2    = (const float*)d_in[4];
    const float* w_ih  = (const float*)d_in[5];
    const float* b_ih  = (const float*)d_in[6];
    const float* w_hh  = (const float*)d_in[7];
    const float* b_hh  = (const float*)d_in[8];
    const float* out_w = (const float*)d_in[9];
    const float* out_b = (const float*)d_in[10];
    float* out = (float*)d_out;

    int T = (out_size - B_ * H_) / (B_ * DOUT_);   // = 256
    if (T > T_) T = T_;

    static bool attr_done = false;
    if (!attr_done) {
        cudaFuncSetAttribute(gru_kernel,
                             cudaFuncAttributeMaxDynamicSharedMemorySize, R_SMEM);
        attr_done = true;
    }

    split_all_kernel<<<(SPLIT_TOTAL + 255) / 256, 256>>>(x, w1, w2, out_w);
    wprep4_kernel<<<4 * H_, 256>>>(w_ih, w_hh);

    // FCN layer 1: t1 = x @ w1^T + b1
    gemm3_kernel<<<dim3(H_ / 64, B_ / 128), 256>>>(0, b1, nullptr, B_, H_, DIN_, 0);
    // FCN layer 2: latent -> d_out latent slice + hs slab 0
    gemm3_kernel<<<dim3(H_ / 64, B_ / 128), 256>>>(
        1, b2, out + (size_t)B_ * T * DOUT_, B_, H_, H_, 1);

    // GRU recurrence (gate-merged r14 math, BK=64: 16 tiles, half the barriers)
    for (int t = 0; t < T; t++)
        gru_kernel<<<dim3(H_ / 16, B_ / 64), 256, R_SMEM>>>(t, b_ih, b_hh);

    // Output projection (permuted write)
    gemm3_kernel<<<dim3(DOUT_ / 64, (T * B_) / 128), 256>>>(
        2, out_b, out, T * B_, DOUT_, H_, 2);
}